// round 16
// baseline (speedup 1.0000x reference)
#include <cuda_runtime.h>
#include <cuda_bf16.h>
#include <math.h>
#include <stdint.h>

#define NN 20000
#define EE 320000
#define HD 256     // H*D
#define NH 8       // heads
#define DH 32      // dim per head
#define CAP 64     // bucket capacity per node (P(deg>=64) ~ 1e-20 for Poisson(16))

// ---------------- scratch (device globals; no allocation allowed) ----------
__device__ float g_h[NN * HD];        // post-GEMM features of current layer
__device__ float g_x1[NN * HD];       // layer-1 output
__device__ float g_el[NN * NH];
__device__ float g_er[NN * NH];
__device__ int   g_cnt[NN];           // per-node in-degree (atomic cursor)
__device__ int   g_bucket[NN * CAP];  // src node ids, bucketed by dst

// ---------------- bucket CSR: zero + scatter only --------------------------
__global__ void zero_kernel() {
    int i = blockIdx.x * blockDim.x + threadIdx.x;
    if (i < NN) g_cnt[i] = 0;
}

__global__ void scatter_kernel(const int* __restrict__ src,
                               const int* __restrict__ dst) {
    int e = blockIdx.x * blockDim.x + threadIdx.x;
    if (e < EE) {
        int d = dst[e];
        int p = atomicAdd(&g_cnt[d], 1);
        if (p < CAP) g_bucket[d * CAP + p] = src[e];
    }
}

// ---------------- TF32 tensor-core GEMM, cp.async double-buffered ----------
#define PA 36
#define PB 136
#define ASZ (128 * PA)
#define BSZ (32 * PB)
#define GEMM_SMEM ((2 * ASZ + 2 * BSZ) * 4)

__device__ __forceinline__ uint32_t f2tf(float x) {
    uint32_t u;
    asm("cvt.rna.tf32.f32 %0, %1;" : "=r"(u) : "f"(x));
    return u;
}

__device__ __forceinline__ void cp16(uint32_t saddr, const void* gptr, bool valid) {
    int sz = valid ? 16 : 0;
    asm volatile("cp.async.cg.shared.global [%0], [%1], 16, %2;"
                 :: "r"(saddr), "l"(gptr), "r"(sz));
}

__device__ __forceinline__ void mma8(float* c, const uint32_t* a, const uint32_t* b) {
    asm volatile(
        "mma.sync.aligned.m16n8k8.row.col.f32.tf32.tf32.f32 "
        "{%0,%1,%2,%3}, {%4,%5,%6,%7}, {%8,%9}, {%0,%1,%2,%3};"
        : "+f"(c[0]), "+f"(c[1]), "+f"(c[2]), "+f"(c[3])
        : "r"(a[0]), "r"(a[1]), "r"(a[2]), "r"(a[3]),
          "r"(b[0]), "r"(b[1]));
}

__global__ void __launch_bounds__(256)
gemm_tf32_kernel(const float* __restrict__ X, const float* __restrict__ W,
                 const float* __restrict__ al, const float* __restrict__ ar,
                 float* __restrict__ Hout) {
    extern __shared__ float smem[];
    float* As = smem;                 // [2][ASZ]
    float* Bs = smem + 2 * ASZ;       // [2][BSZ]

    int tid = threadIdx.x;
    int warp = tid >> 5, lane = tid & 31;
    int g = lane >> 2, t4 = lane & 3;
    int wm = (warp & 3) * 32;
    int wn = (warp >> 2) * 64;
    int m0 = blockIdx.x * 128;
    int n0 = blockIdx.y * 128;

    int arow[4], ac4[4], brow[4], bc4[4];
    #pragma unroll
    for (int i = 0; i < 4; i++) {
        int idx = tid + i * 256;
        arow[i] = idx >> 3;  ac4[i] = (idx & 7) * 4;
        brow[i] = idx >> 5;  bc4[i] = (idx & 31) * 4;
    }

    float acc[2][8][4];
    #pragma unroll
    for (int mf = 0; mf < 2; mf++)
        #pragma unroll
        for (int nf = 0; nf < 8; nf++)
            #pragma unroll
            for (int i = 0; i < 4; i++) acc[mf][nf][i] = 0.f;

    uint32_t sA = (uint32_t)__cvta_generic_to_shared(As);
    uint32_t sB = (uint32_t)__cvta_generic_to_shared(Bs);

    #define LOAD_TILE(k0, st)                                                   \
    do {                                                                        \
        _Pragma("unroll")                                                       \
        for (int i = 0; i < 4; i++) {                                           \
            int grow = m0 + arow[i];                                            \
            cp16(sA + ((st) * ASZ + arow[i] * PA + ac4[i]) * 4,                 \
                 X + (size_t)grow * 256 + (k0) + ac4[i], grow < NN);            \
        }                                                                       \
        _Pragma("unroll")                                                       \
        for (int i = 0; i < 4; i++) {                                           \
            cp16(sB + ((st) * BSZ + brow[i] * PB + bc4[i]) * 4,                 \
                 W + (size_t)((k0) + brow[i]) * 256 + n0 + bc4[i], true);       \
        }                                                                       \
        asm volatile("cp.async.commit_group;");                                 \
    } while (0)

    LOAD_TILE(0, 0);

    #pragma unroll 1
    for (int kt = 0; kt < 8; kt++) {
        int st = kt & 1;
        if (kt < 7) LOAD_TILE((kt + 1) * 32, st ^ 1);
        if (kt < 7) asm volatile("cp.async.wait_group 1;");
        else        asm volatile("cp.async.wait_group 0;");
        __syncthreads();

        const float* Af = As + st * ASZ;
        const float* Bf = Bs + st * BSZ;

        #pragma unroll
        for (int k8 = 0; k8 < 32; k8 += 8) {
            uint32_t a[2][4], b[8][2];
            #pragma unroll
            for (int mf = 0; mf < 2; mf++) {
                int r = wm + mf * 16 + g;
                a[mf][0] = f2tf(Af[r * PA + k8 + t4]);
                a[mf][1] = f2tf(Af[(r + 8) * PA + k8 + t4]);
                a[mf][2] = f2tf(Af[r * PA + k8 + t4 + 4]);
                a[mf][3] = f2tf(Af[(r + 8) * PA + k8 + t4 + 4]);
            }
            #pragma unroll
            for (int nf = 0; nf < 8; nf++) {
                int c = wn + nf * 8 + g;
                b[nf][0] = f2tf(Bf[(k8 + t4) * PB + c]);
                b[nf][1] = f2tf(Bf[(k8 + t4 + 4) * PB + c]);
            }
            #pragma unroll
            for (int mf = 0; mf < 2; mf++)
                #pragma unroll
                for (int nf = 0; nf < 8; nf++)
                    mma8(acc[mf][nf], a[mf], b[nf]);
        }
        __syncthreads();
    }

    // ---- fused epilogue: Hout stores + el/er logits -----------------------
    float pel[2][2][2], per[2][2][2];
    #pragma unroll
    for (int mf = 0; mf < 2; mf++)
        #pragma unroll
        for (int rh = 0; rh < 2; rh++)
            #pragma unroll
            for (int hl = 0; hl < 2; hl++) { pel[mf][rh][hl] = 0.f; per[mf][rh][hl] = 0.f; }

    #pragma unroll
    for (int mf = 0; mf < 2; mf++) {
        #pragma unroll
        for (int nf = 0; nf < 8; nf++) {
            int col = n0 + wn + nf * 8 + 2 * t4;
            int row0 = m0 + wm + mf * 16 + g;
            if (row0 < NN)
                *(float2*)(Hout + (size_t)row0 * 256 + col) =
                    make_float2(acc[mf][nf][0], acc[mf][nf][1]);
            int row1 = row0 + 8;
            if (row1 < NN)
                *(float2*)(Hout + (size_t)row1 * 256 + col) =
                    make_float2(acc[mf][nf][2], acc[mf][nf][3]);

            float a0 = al[col], a1 = al[col + 1];
            float r0 = ar[col], r1 = ar[col + 1];
            int hl = nf >> 2;
            pel[mf][0][hl] += acc[mf][nf][0] * a0 + acc[mf][nf][1] * a1;
            pel[mf][1][hl] += acc[mf][nf][2] * a0 + acc[mf][nf][3] * a1;
            per[mf][0][hl] += acc[mf][nf][0] * r0 + acc[mf][nf][1] * r1;
            per[mf][1][hl] += acc[mf][nf][2] * r0 + acc[mf][nf][3] * r1;
        }
    }
    #pragma unroll
    for (int mf = 0; mf < 2; mf++)
        #pragma unroll
        for (int rh = 0; rh < 2; rh++)
            #pragma unroll
            for (int hl = 0; hl < 2; hl++) {
                float v = pel[mf][rh][hl];
                v += __shfl_xor_sync(0xffffffffu, v, 1);
                v += __shfl_xor_sync(0xffffffffu, v, 2);
                pel[mf][rh][hl] = v;
                float u = per[mf][rh][hl];
                u += __shfl_xor_sync(0xffffffffu, u, 1);
                u += __shfl_xor_sync(0xffffffffu, u, 2);
                per[mf][rh][hl] = u;
            }
    if (t4 == 0) {
        int headbase = (n0 + wn) >> 5;
        #pragma unroll
        for (int mf = 0; mf < 2; mf++) {
            #pragma unroll
            for (int rh = 0; rh < 2; rh++) {
                int row = m0 + wm + mf * 16 + g + rh * 8;
                if (row < NN) {
                    #pragma unroll
                    for (int hl = 0; hl < 2; hl++) {
                        g_el[row * 8 + headbase + hl] = pel[mf][rh][hl];
                        g_er[row * 8 + headbase + hl] = per[mf][rh][hl];
                    }
                }
            }
        }
    }
}

// ---------------- fused softmax + aggregation: one warp per dst node -------
// Phase 1: lanes own bucket slots lane / lane+32 (sequential halves, low reg
// pressure); raw exp-weights to smem; butterfly sums; 2 reciprocals per lane.
// Phase 2: 4-edge-unrolled float4 gather+FMA (8 independent LDG.128 in
// flight per warp); normalize acc once at the end.
__global__ void __launch_bounds__(256)
agg_fused_kernel(const float* __restrict__ Hm, const float* __restrict__ bias,
                 float* __restrict__ out) {
    __shared__ float s_w[8][CAP][NH];   // raw exp weights, 16 KB
    __shared__ int   s_idx[8][CAP];     // 2 KB

    int wi = threadIdx.x >> 5;
    int w = blockIdx.x * 8 + wi;
    int lane = threadIdx.x & 31;
    if (w >= NN) return;

    int cnt = g_cnt[w];
    if (cnt > CAP) cnt = CAP;

    float er8[8];
    {
        float4 e0 = ((const float4*)g_er)[w * 2];
        float4 e1 = ((const float4*)g_er)[w * 2 + 1];
        er8[0] = e0.x; er8[1] = e0.y; er8[2] = e0.z; er8[3] = e0.w;
        er8[4] = e1.x; er8[5] = e1.y; er8[6] = e1.z; er8[7] = e1.w;
    }

    const float4* el4 = (const float4*)g_el;
    float sum[8];
    #pragma unroll
    for (int j = 0; j < 8; j++) sum[j] = 0.f;

    #pragma unroll
    for (int half = 0; half < 2; half++) {
        int slot = lane + half * 32;
        if (slot < cnt) {
            int s = g_bucket[w * CAP + slot];
            s_idx[wi][slot] = s;
            float4 l0 = el4[s * 2], l1 = el4[s * 2 + 1];
            float ee[8] = {l0.x, l0.y, l0.z, l0.w, l1.x, l1.y, l1.z, l1.w};
            #pragma unroll
            for (int j = 0; j < 8; j++) {
                float e = ee[j] + er8[j]; e = e > 0.f ? e : 0.2f * e;
                float wv = __expf(e);
                sum[j] += wv;
                s_w[wi][slot][j] = wv;
            }
        }
    }

    #pragma unroll
    for (int off = 16; off; off >>= 1)
        #pragma unroll
        for (int j = 0; j < 8; j++)
            sum[j] += __shfl_xor_sync(0xffffffffu, sum[j], off);

    int hh = lane >> 3;     // head for lower column group
    float rcp0 = (sum[hh] > 0.f) ? 1.f / sum[hh] : 0.f;
    float rcp1 = (sum[4 + hh] > 0.f) ? 1.f / sum[4 + hh] : 0.f;
    __syncwarp();

    // phase 2: 4-edge unrolled float4 gather + FMA on raw weights
    int c0 = lane * 4;
    float4 acc0 = make_float4(0.f, 0.f, 0.f, 0.f);
    float4 acc1 = make_float4(0.f, 0.f, 0.f, 0.f);

    int p = 0;
    for (; p + 4 <= cnt; p += 4) {
        int s0 = s_idx[wi][p],     s1 = s_idx[wi][p + 1];
        int s2 = s_idx[wi][p + 2], s3 = s_idx[wi][p + 3];
        const float4* hp0 = (const float4*)(Hm + (size_t)s0 * 256 + c0);
        const float4* hp1 = (const float4*)(Hm + (size_t)s1 * 256 + c0);
        const float4* hp2 = (const float4*)(Hm + (size_t)s2 * 256 + c0);
        const float4* hp3 = (const float4*)(Hm + (size_t)s3 * 256 + c0);
        float4 v00 = hp0[0], v01 = hp0[32];
        float4 v10 = hp1[0], v11 = hp1[32];
        float4 v20 = hp2[0], v21 = hp2[32];
        float4 v30 = hp3[0], v31 = hp3[32];
        float a00 = s_w[wi][p][hh],     a01 = s_w[wi][p][4 + hh];
        float a10 = s_w[wi][p + 1][hh], a11 = s_w[wi][p + 1][4 + hh];
        float a20 = s_w[wi][p + 2][hh], a21 = s_w[wi][p + 2][4 + hh];
        float a30 = s_w[wi][p + 3][hh], a31 = s_w[wi][p + 3][4 + hh];
        acc0.x += a00 * v00.x + a10 * v10.x + a20 * v20.x + a30 * v30.x;
        acc0.y += a00 * v00.y + a10 * v10.y + a20 * v20.y + a30 * v30.y;
        acc0.z += a00 * v00.z + a10 * v10.z + a20 * v20.z + a30 * v30.z;
        acc0.w += a00 * v00.w + a10 * v10.w + a20 * v20.w + a30 * v30.w;
        acc1.x += a01 * v01.x + a11 * v11.x + a21 * v21.x + a31 * v31.x;
        acc1.y += a01 * v01.y + a11 * v11.y + a21 * v21.y + a31 * v31.y;
        acc1.z += a01 * v01.z + a11 * v11.z + a21 * v21.z + a31 * v31.z;
        acc1.w += a01 * v01.w + a11 * v11.w + a21 * v21.w + a31 * v31.w;
    }
    for (; p < cnt; p++) {
        int s = s_idx[wi][p];
        const float4* hr = (const float4*)(Hm + (size_t)s * 256 + c0);
        float4 v0 = hr[0], v1 = hr[32];
        float a0s = s_w[wi][p][hh], a1s = s_w[wi][p][4 + hh];
        acc0.x += a0s * v0.x; acc0.y += a0s * v0.y;
        acc0.z += a0s * v0.z; acc0.w += a0s * v0.w;
        acc1.x += a1s * v1.x; acc1.y += a1s * v1.y;
        acc1.z += a1s * v1.z; acc1.w += a1s * v1.w;
    }

    float4 b0v = *(const float4*)(bias + c0);
    float4 b1v = *(const float4*)(bias + 128 + c0);
    float o[8] = {acc0.x * rcp0 + b0v.x, acc0.y * rcp0 + b0v.y,
                  acc0.z * rcp0 + b0v.z, acc0.w * rcp0 + b0v.w,
                  acc1.x * rcp1 + b1v.x, acc1.y * rcp1 + b1v.y,
                  acc1.z * rcp1 + b1v.z, acc1.w * rcp1 + b1v.w};
    #pragma unroll
    for (int j = 0; j < 8; j++)
        o[j] = o[j] > 0.f ? o[j] : expm1f(o[j]);
    *(float4*)(out + (size_t)w * 256 + c0)       = make_float4(o[0], o[1], o[2], o[3]);
    *(float4*)(out + (size_t)w * 256 + 128 + c0) = make_float4(o[4], o[5], o[6], o[7]);
}

// ---------------- launcher --------------------------------------------------
extern "C" void kernel_launch(void* const* d_in, const int* in_sizes, int n_in,
                              void* d_out, int out_size) {
    const float* features = (const float*)d_in[0];
    const float* W0 = (const float*)d_in[1];
    const float* al0 = (const float*)d_in[2];
    const float* ar0 = (const float*)d_in[3];
    const float* b0  = (const float*)d_in[4];
    const float* W1 = (const float*)d_in[5];
    const float* al1 = (const float*)d_in[6];
    const float* ar1 = (const float*)d_in[7];
    const float* b1  = (const float*)d_in[8];
    const int* src = (const int*)d_in[9];
    const int* dst = (const int*)d_in[10];
    float* out = (float*)d_out;

    float *hp, *x1p;
    cudaGetSymbolAddress((void**)&hp, g_h);
    cudaGetSymbolAddress((void**)&x1p, g_x1);

    cudaFuncSetAttribute(gemm_tf32_kernel,
                         cudaFuncAttributeMaxDynamicSharedMemorySize, GEMM_SMEM);

    // bucket adjacency (shared by both layers)
    zero_kernel<<<(NN + 255) / 256, 256>>>();
    scatter_kernel<<<(EE + 255) / 256, 256>>>(src, dst);

    dim3 ggrid((NN + 127) / 128, 2);

    // layer 1
    gemm_tf32_kernel<<<ggrid, 256, GEMM_SMEM>>>(features, W0, al0, ar0, hp);
    agg_fused_kernel<<<2500, 256>>>(hp, b0, x1p);

    // layer 2
    gemm_tf32_kernel<<<ggrid, 256, GEMM_SMEM>>>(x1p, W1, al1, ar1, hp);
    agg_fused_kernel<<<2500, 256>>>(hp, b1, out);
}

// round 17
// speedup vs baseline: 1.0563x; 1.0563x over previous
#include <cuda_runtime.h>
#include <cuda_bf16.h>
#include <math.h>
#include <stdint.h>

#define NN 20000
#define EE 320000
#define HD 256     // H*D
#define NH 8       // heads
#define DH 32      // dim per head
#define CAP 64     // bucket capacity per node (P(deg>=64) ~ 1e-20 for Poisson(16))
#define WPB 4      // warps per agg block

// ---------------- scratch (device globals; no allocation allowed) ----------
// NOTE: __device__ globals are zero-initialized at module load; g_cnt is
// re-zeroed by the layer-2 agg kernel each launch, so no zero_kernel needed.
__device__ float g_h[NN * HD];        // post-GEMM features of current layer
__device__ float g_x1[NN * HD];       // layer-1 output
__device__ float g_el[NN * NH];
__device__ float g_er[NN * NH];
__device__ int   g_cnt[NN];           // per-node in-degree (atomic cursor)
__device__ int   g_bucket[NN * CAP];  // src node ids, bucketed by dst

// ---------------- bucket CSR: scatter only ---------------------------------
__global__ void scatter_kernel(const int* __restrict__ src,
                               const int* __restrict__ dst) {
    int e = blockIdx.x * blockDim.x + threadIdx.x;
    if (e < EE) {
        int d = dst[e];
        int p = atomicAdd(&g_cnt[d], 1);
        if (p < CAP) g_bucket[d * CAP + p] = src[e];
    }
}

// ---------------- TF32 tensor-core GEMM, cp.async double-buffered ----------
#define PA 36
#define PB 136
#define ASZ (128 * PA)
#define BSZ (32 * PB)
#define GEMM_SMEM ((2 * ASZ + 2 * BSZ) * 4)

__device__ __forceinline__ uint32_t f2tf(float x) {
    uint32_t u;
    asm("cvt.rna.tf32.f32 %0, %1;" : "=r"(u) : "f"(x));
    return u;
}

__device__ __forceinline__ void cp16(uint32_t saddr, const void* gptr, bool valid) {
    int sz = valid ? 16 : 0;
    asm volatile("cp.async.cg.shared.global [%0], [%1], 16, %2;"
                 :: "r"(saddr), "l"(gptr), "r"(sz));
}

__device__ __forceinline__ void mma8(float* c, const uint32_t* a, const uint32_t* b) {
    asm volatile(
        "mma.sync.aligned.m16n8k8.row.col.f32.tf32.tf32.f32 "
        "{%0,%1,%2,%3}, {%4,%5,%6,%7}, {%8,%9}, {%0,%1,%2,%3};"
        : "+f"(c[0]), "+f"(c[1]), "+f"(c[2]), "+f"(c[3])
        : "r"(a[0]), "r"(a[1]), "r"(a[2]), "r"(a[3]),
          "r"(b[0]), "r"(b[1]));
}

__global__ void __launch_bounds__(256)
gemm_tf32_kernel(const float* __restrict__ X, const float* __restrict__ W,
                 const float* __restrict__ al, const float* __restrict__ ar,
                 float* __restrict__ Hout) {
    extern __shared__ float smem[];
    float* As = smem;                 // [2][ASZ]
    float* Bs = smem + 2 * ASZ;       // [2][BSZ]

    int tid = threadIdx.x;
    int warp = tid >> 5, lane = tid & 31;
    int g = lane >> 2, t4 = lane & 3;
    int wm = (warp & 3) * 32;
    int wn = (warp >> 2) * 64;
    int m0 = blockIdx.x * 128;
    int n0 = blockIdx.y * 128;

    int arow[4], ac4[4], brow[4], bc4[4];
    #pragma unroll
    for (int i = 0; i < 4; i++) {
        int idx = tid + i * 256;
        arow[i] = idx >> 3;  ac4[i] = (idx & 7) * 4;
        brow[i] = idx >> 5;  bc4[i] = (idx & 31) * 4;
    }

    float acc[2][8][4];
    #pragma unroll
    for (int mf = 0; mf < 2; mf++)
        #pragma unroll
        for (int nf = 0; nf < 8; nf++)
            #pragma unroll
            for (int i = 0; i < 4; i++) acc[mf][nf][i] = 0.f;

    uint32_t sA = (uint32_t)__cvta_generic_to_shared(As);
    uint32_t sB = (uint32_t)__cvta_generic_to_shared(Bs);

    #define LOAD_TILE(k0, st)                                                   \
    do {                                                                        \
        _Pragma("unroll")                                                       \
        for (int i = 0; i < 4; i++) {                                           \
            int grow = m0 + arow[i];                                            \
            cp16(sA + ((st) * ASZ + arow[i] * PA + ac4[i]) * 4,                 \
                 X + (size_t)grow * 256 + (k0) + ac4[i], grow < NN);            \
        }                                                                       \
        _Pragma("unroll")                                                       \
        for (int i = 0; i < 4; i++) {                                           \
            cp16(sB + ((st) * BSZ + brow[i] * PB + bc4[i]) * 4,                 \
                 W + (size_t)((k0) + brow[i]) * 256 + n0 + bc4[i], true);       \
        }                                                                       \
        asm volatile("cp.async.commit_group;");                                 \
    } while (0)

    LOAD_TILE(0, 0);

    #pragma unroll 1
    for (int kt = 0; kt < 8; kt++) {
        int st = kt & 1;
        if (kt < 7) LOAD_TILE((kt + 1) * 32, st ^ 1);
        if (kt < 7) asm volatile("cp.async.wait_group 1;");
        else        asm volatile("cp.async.wait_group 0;");
        __syncthreads();

        const float* Af = As + st * ASZ;
        const float* Bf = Bs + st * BSZ;

        #pragma unroll
        for (int k8 = 0; k8 < 32; k8 += 8) {
            uint32_t a[2][4], b[8][2];
            #pragma unroll
            for (int mf = 0; mf < 2; mf++) {
                int r = wm + mf * 16 + g;
                a[mf][0] = f2tf(Af[r * PA + k8 + t4]);
                a[mf][1] = f2tf(Af[(r + 8) * PA + k8 + t4]);
                a[mf][2] = f2tf(Af[r * PA + k8 + t4 + 4]);
                a[mf][3] = f2tf(Af[(r + 8) * PA + k8 + t4 + 4]);
            }
            #pragma unroll
            for (int nf = 0; nf < 8; nf++) {
                int c = wn + nf * 8 + g;
                b[nf][0] = f2tf(Bf[(k8 + t4) * PB + c]);
                b[nf][1] = f2tf(Bf[(k8 + t4 + 4) * PB + c]);
            }
            #pragma unroll
            for (int mf = 0; mf < 2; mf++)
                #pragma unroll
                for (int nf = 0; nf < 8; nf++)
                    mma8(acc[mf][nf], a[mf], b[nf]);
        }
        __syncthreads();
    }

    // ---- fused epilogue: Hout stores + el/er logits -----------------------
    float pel[2][2][2], per[2][2][2];
    #pragma unroll
    for (int mf = 0; mf < 2; mf++)
        #pragma unroll
        for (int rh = 0; rh < 2; rh++)
            #pragma unroll
            for (int hl = 0; hl < 2; hl++) { pel[mf][rh][hl] = 0.f; per[mf][rh][hl] = 0.f; }

    #pragma unroll
    for (int mf = 0; mf < 2; mf++) {
        #pragma unroll
        for (int nf = 0; nf < 8; nf++) {
            int col = n0 + wn + nf * 8 + 2 * t4;
            int row0 = m0 + wm + mf * 16 + g;
            if (row0 < NN)
                *(float2*)(Hout + (size_t)row0 * 256 + col) =
                    make_float2(acc[mf][nf][0], acc[mf][nf][1]);
            int row1 = row0 + 8;
            if (row1 < NN)
                *(float2*)(Hout + (size_t)row1 * 256 + col) =
                    make_float2(acc[mf][nf][2], acc[mf][nf][3]);

            float a0 = al[col], a1 = al[col + 1];
            float r0 = ar[col], r1 = ar[col + 1];
            int hl = nf >> 2;
            pel[mf][0][hl] += acc[mf][nf][0] * a0 + acc[mf][nf][1] * a1;
            pel[mf][1][hl] += acc[mf][nf][2] * a0 + acc[mf][nf][3] * a1;
            per[mf][0][hl] += acc[mf][nf][0] * r0 + acc[mf][nf][1] * r1;
            per[mf][1][hl] += acc[mf][nf][2] * r0 + acc[mf][nf][3] * r1;
        }
    }
    #pragma unroll
    for (int mf = 0; mf < 2; mf++)
        #pragma unroll
        for (int rh = 0; rh < 2; rh++)
            #pragma unroll
            for (int hl = 0; hl < 2; hl++) {
                float v = pel[mf][rh][hl];
                v += __shfl_xor_sync(0xffffffffu, v, 1);
                v += __shfl_xor_sync(0xffffffffu, v, 2);
                pel[mf][rh][hl] = v;
                float u = per[mf][rh][hl];
                u += __shfl_xor_sync(0xffffffffu, u, 1);
                u += __shfl_xor_sync(0xffffffffu, u, 2);
                per[mf][rh][hl] = u;
            }
    if (t4 == 0) {
        int headbase = (n0 + wn) >> 5;
        #pragma unroll
        for (int mf = 0; mf < 2; mf++) {
            #pragma unroll
            for (int rh = 0; rh < 2; rh++) {
                int row = m0 + wm + mf * 16 + g + rh * 8;
                if (row < NN) {
                    #pragma unroll
                    for (int hl = 0; hl < 2; hl++) {
                        g_el[row * 8 + headbase + hl] = pel[mf][rh][hl];
                        g_er[row * 8 + headbase + hl] = per[mf][rh][hl];
                    }
                }
            }
        }
    }
}

// ---------------- fused softmax + aggregation: one warp per dst node -------
// 128-thread blocks (4 warps) for high occupancy (regs ~40 -> ~12 blocks/SM).
// Phase 1: lanes own bucket slots lane / lane+32 (sequential halves); raw
// exp-weights to smem; butterfly sums; 2 reciprocals per lane.
// Phase 2: 2-edge float4 gather+FMA; normalize acc at the end.
// clear!=0 (layer 2): reset g_cnt[w]=0 after last use -> next launch needs
// no zero_kernel.
__global__ void __launch_bounds__(128)
agg_fused_kernel(const float* __restrict__ Hm, const float* __restrict__ bias,
                 float* __restrict__ out, int clear) {
    __shared__ float s_w[WPB][CAP][NH];   // raw exp weights, 8 KB
    __shared__ int   s_idx[WPB][CAP];     // 1 KB

    int wi = threadIdx.x >> 5;
    int w = blockIdx.x * WPB + wi;
    int lane = threadIdx.x & 31;
    if (w >= NN) return;

    int cnt = g_cnt[w];
    if (cnt > CAP) cnt = CAP;

    float er8[8];
    {
        float4 e0 = ((const float4*)g_er)[w * 2];
        float4 e1 = ((const float4*)g_er)[w * 2 + 1];
        er8[0] = e0.x; er8[1] = e0.y; er8[2] = e0.z; er8[3] = e0.w;
        er8[4] = e1.x; er8[5] = e1.y; er8[6] = e1.z; er8[7] = e1.w;
    }

    const float4* el4 = (const float4*)g_el;
    float sum[8];
    #pragma unroll
    for (int j = 0; j < 8; j++) sum[j] = 0.f;

    #pragma unroll
    for (int half = 0; half < 2; half++) {
        int slot = lane + half * 32;
        if (slot < cnt) {
            int s = g_bucket[w * CAP + slot];
            s_idx[wi][slot] = s;
            float4 l0 = el4[s * 2], l1 = el4[s * 2 + 1];
            float ee[8] = {l0.x, l0.y, l0.z, l0.w, l1.x, l1.y, l1.z, l1.w};
            #pragma unroll
            for (int j = 0; j < 8; j++) {
                float e = ee[j] + er8[j]; e = e > 0.f ? e : 0.2f * e;
                float wv = __expf(e);
                sum[j] += wv;
                s_w[wi][slot][j] = wv;
            }
        }
    }

    #pragma unroll
    for (int off = 16; off; off >>= 1)
        #pragma unroll
        for (int j = 0; j < 8; j++)
            sum[j] += __shfl_xor_sync(0xffffffffu, sum[j], off);

    int hh = lane >> 3;
    float rcp0 = (sum[hh] > 0.f) ? 1.f / sum[hh] : 0.f;
    float rcp1 = (sum[4 + hh] > 0.f) ? 1.f / sum[4 + hh] : 0.f;
    __syncwarp();

    // phase 2: 2-edge float4 gather + FMA on raw weights
    int c0 = lane * 4;
    float4 acc0 = make_float4(0.f, 0.f, 0.f, 0.f);
    float4 acc1 = make_float4(0.f, 0.f, 0.f, 0.f);

    int p = 0;
    for (; p + 2 <= cnt; p += 2) {
        int sA_ = s_idx[wi][p], sB_ = s_idx[wi][p + 1];
        const float4* hA = (const float4*)(Hm + (size_t)sA_ * 256 + c0);
        const float4* hB = (const float4*)(Hm + (size_t)sB_ * 256 + c0);
        float4 vA0 = hA[0], vA1 = hA[32];
        float4 vB0 = hB[0], vB1 = hB[32];
        float aA0 = s_w[wi][p][hh],     aA1 = s_w[wi][p][4 + hh];
        float aB0 = s_w[wi][p + 1][hh], aB1 = s_w[wi][p + 1][4 + hh];
        acc0.x += aA0 * vA0.x + aB0 * vB0.x;
        acc0.y += aA0 * vA0.y + aB0 * vB0.y;
        acc0.z += aA0 * vA0.z + aB0 * vB0.z;
        acc0.w += aA0 * vA0.w + aB0 * vB0.w;
        acc1.x += aA1 * vA1.x + aB1 * vB1.x;
        acc1.y += aA1 * vA1.y + aB1 * vB1.y;
        acc1.z += aA1 * vA1.z + aB1 * vB1.z;
        acc1.w += aA1 * vA1.w + aB1 * vB1.w;
    }
    if (p < cnt) {
        int s = s_idx[wi][p];
        const float4* hr = (const float4*)(Hm + (size_t)s * 256 + c0);
        float4 v0 = hr[0], v1 = hr[32];
        float a0s = s_w[wi][p][hh], a1s = s_w[wi][p][4 + hh];
        acc0.x += a0s * v0.x; acc0.y += a0s * v0.y;
        acc0.z += a0s * v0.z; acc0.w += a0s * v0.w;
        acc1.x += a1s * v1.x; acc1.y += a1s * v1.y;
        acc1.z += a1s * v1.z; acc1.w += a1s * v1.w;
    }

    float4 b0v = *(const float4*)(bias + c0);
    float4 b1v = *(const float4*)(bias + 128 + c0);
    float o[8] = {acc0.x * rcp0 + b0v.x, acc0.y * rcp0 + b0v.y,
                  acc0.z * rcp0 + b0v.z, acc0.w * rcp0 + b0v.w,
                  acc1.x * rcp1 + b1v.x, acc1.y * rcp1 + b1v.y,
                  acc1.z * rcp1 + b1v.z, acc1.w * rcp1 + b1v.w};
    #pragma unroll
    for (int j = 0; j < 8; j++)
        o[j] = o[j] > 0.f ? o[j] : expm1f(o[j]);
    *(float4*)(out + (size_t)w * 256 + c0)       = make_float4(o[0], o[1], o[2], o[3]);
    *(float4*)(out + (size_t)w * 256 + 128 + c0) = make_float4(o[4], o[5], o[6], o[7]);

    // self-clean for the next launch (layer-2 only; after last g_cnt use)
    if (clear && lane == 0) g_cnt[w] = 0;
}

// ---------------- launcher --------------------------------------------------
extern "C" void kernel_launch(void* const* d_in, const int* in_sizes, int n_in,
                              void* d_out, int out_size) {
    const float* features = (const float*)d_in[0];
    const float* W0 = (const float*)d_in[1];
    const float* al0 = (const float*)d_in[2];
    const float* ar0 = (const float*)d_in[3];
    const float* b0  = (const float*)d_in[4];
    const float* W1 = (const float*)d_in[5];
    const float* al1 = (const float*)d_in[6];
    const float* ar1 = (const float*)d_in[7];
    const float* b1  = (const float*)d_in[8];
    const int* src = (const int*)d_in[9];
    const int* dst = (const int*)d_in[10];
    float* out = (float*)d_out;

    float *hp, *x1p;
    cudaGetSymbolAddress((void**)&hp, g_h);
    cudaGetSymbolAddress((void**)&x1p, g_x1);

    cudaFuncSetAttribute(gemm_tf32_kernel,
                         cudaFuncAttributeMaxDynamicSharedMemorySize, GEMM_SMEM);

    // bucket adjacency (g_cnt is zero: static init on first run, then
    // self-cleaned by the previous launch's layer-2 agg)
    scatter_kernel<<<(EE + 255) / 256, 256>>>(src, dst);

    dim3 ggrid((NN + 127) / 128, 2);

    // layer 1
    gemm_tf32_kernel<<<ggrid, 256, GEMM_SMEM>>>(features, W0, al0, ar0, hp);
    agg_fused_kernel<<<NN / WPB, 128>>>(hp, b0, x1p, 0);

    // layer 2
    gemm_tf32_kernel<<<ggrid, 256, GEMM_SMEM>>>(x1p, W1, al1, ar1, hp);
    agg_fused_kernel<<<NN / WPB, 128>>>(hp, b1, out, 1);
}